// round 4
// baseline (speedup 1.0000x reference)
#include <cuda_runtime.h>
#include <math.h>

#define NPIX   262144
#define NCH    256
#define NQ     64            // float4 quads per channel row
#define NK     24            // n_knots + degree + 1
#define ND     22            // second-difference rows
#define PPI    16            // pixels per tile
#define NTILES (NPIX / PPI)  // 16384
#define GRID   444           // 148 SMs * 3 resident blocks

#define C1F 1.191042e-08f
#define C2F 1.4387769f

// ---------------- persistent device scratch (no allocations) ----------------
__device__ double   g_res;
__device__ double   g_ss;
__device__ double   g_bv;
__device__ unsigned g_count;

__global__ void __launch_bounds__(256, 3)
fused_kernel(const float4* __restrict__ s_obs,
             const float*  __restrict__ temperature,
             const float*  __restrict__ beta,
             const float*  __restrict__ view_factor,
             const float*  __restrict__ s_sky,
             const float*  __restrict__ s_ground,
             const float*  __restrict__ phi,
             const float*  __restrict__ wn,
             float*  __restrict__ s_model,     // 4-byte aligned only (d_out+1)!
             float*  __restrict__ out_total,
             int write_total)
{
    __shared__ float sb[2][PPI * NK];   // beta tiles (double buffered)
    __shared__ float sT[2][PPI];        // 1/T
    __shared__ float sV[2][PPI];        // view factor
    __shared__ float wred[3][8];

    const int t    = threadIdx.x;
    const int q    = t & 63;            // channel quad -> channels 4q..4q+3
    const int pr   = t >> 6;            // pixel row slot 0..3
    const int wid  = t >> 5;
    const int lane = t & 31;

    // ---- per-thread constants for 4 channels (one-time) ----
    float w[4][4], c1[4], sg4[4], dsg4[4];
    int   k0[4];
    #pragma unroll
    for (int i = 0; i < 4; ++i) {
        const int c = 4 * q + i;
        const float* row = phi + c * NK;
        int k = 0;
        for (int kk = 0; kk < NK; ++kk) {
            if (row[kk] != 0.0f) { k = kk; break; }
        }
        if (k > NK - 4) k = NK - 4;
        k0[i] = k;
        w[i][0] = row[k];     w[i][1] = row[k + 1];
        w[i][2] = row[k + 2]; w[i][3] = row[k + 3];
        const float v = wn[c];
        c1[i] = C1F * v * v * v;
        const float s = s_ground[c];
        sg4[i]  = s;
        dsg4[i] = s_sky[c] - s;
    }
    const float av  = C2F * wn[4 * q];          // C2 * v_first
    const float adv = C2F * (wn[1] - wn[0]);    // C2 * dv (uniform grid)

    // smoothness work assignment: indices t and t+256 of PPI*ND=352
    const int sp_a = t / ND,         sj_a = t - sp_a * ND;
    const int sp_b = (t + 256) / ND, sj_b = (t + 256) - sp_b * ND;
    const bool has_b = (t + 256) < PPI * ND;

    float rs = 0.0f, bvs = 0.0f, sss = 0.0f;

    // staging: beta = PPI*NK = 384 floats (2 passes), T/vf by threads 128..159
    auto stage = [&](int buf, int tile) {
        const int base = tile * PPI;
        sb[buf][t] = __ldcs(&beta[base * NK + t]);
        if (t < 128) {
            sb[buf][256 + t] = __ldcs(&beta[base * NK + 256 + t]);
        } else if (t < 128 + PPI) {
            sT[buf][t - 128] = __frcp_rn(temperature[base + (t - 128)]);
        } else if (t < 128 + 2 * PPI) {
            sV[buf][t - 128 - PPI] = view_factor[base + (t - 128 - PPI)];
        }
    };

    int tile = blockIdx.x;
    stage(0, tile);
    __syncthreads();

    int buf = 0;
    for (; tile < NTILES; tile += GRID) {
        const int nxt = tile + GRID;
        if (nxt < NTILES) stage(buf ^ 1, nxt);

        const int base = tile * PPI;

        // smoothness from staged tile
        {
            const float* ba = &sb[buf][sp_a * NK];
            float d = ba[sj_a] - 2.0f * ba[sj_a + 1] + ba[sj_a + 2];
            sss = fmaf(d, d, sss);
            if (has_b) {
                const float* bb = &sb[buf][sp_b * NK];
                d = bb[sj_b] - 2.0f * bb[sj_b + 1] + bb[sj_b + 2];
                sss = fmaf(d, d, sss);
            }
        }

        // prefetch s_obs (4 float4 rows per thread -> 64B in flight)
        float4 so4[4];
        #pragma unroll
        for (int jj = 0; jj < 4; ++jj) {
            const int p = pr + 4 * jj;
            so4[jj] = __ldcs(&s_obs[(size_t)(base + p) * NQ + q]);
        }

        #pragma unroll
        for (int jj = 0; jj < 4; ++jj) {
            const int p = pr + 4 * jj;
            const float* b = &sb[buf][p * NK];
            const float invT = sT[buf][p];
            const float vf   = sV[buf][p];

            // emissivity for 4 channels
            float e[4];
            #pragma unroll
            for (int i = 0; i < 4; ++i) {
                float acc = w[i][0] * b[k0[i]];
                acc = fmaf(w[i][1], b[k0[i] + 1], acc);
                acc = fmaf(w[i][2], b[k0[i] + 2], acc);
                e[i] = fmaf(w[i][3], b[k0[i] + 3], acc);
            }

            // Planck via geometric recurrence: E_i = E0 * r^i
            const float E0 = __expf(av * invT);
            const float r  = __expf(adv * invT);
            float E[4];
            E[0] = E0; E[1] = E0 * r; E[2] = E[1] * r; E[3] = E[2] * r;

            float sm[4];
            #pragma unroll
            for (int i = 0; i < 4; ++i) {
                const float pl = __fdividef(c1[i], E[i] - 1.0f); // arg>=2.3
                const float xa = fmaf(vf, dsg4[i], sg4[i]);
                sm[i] = fmaf(e[i], pl - xa, xa);
                bvs += fmaxf(fmaxf(0.01f - e[i], e[i] - 0.99f), 0.0f);
            }

            // scalar stores: s_model base is only 4B aligned (d_out + 1)
            float* outp = &s_model[((size_t)(base + p) * NQ + q) * 4];
            __stcs(outp + 0, sm[0]);
            __stcs(outp + 1, sm[1]);
            __stcs(outp + 2, sm[2]);
            __stcs(outp + 3, sm[3]);

            const float d0 = so4[jj].x - sm[0];
            const float d1 = so4[jj].y - sm[1];
            const float d2 = so4[jj].z - sm[2];
            const float d3 = so4[jj].w - sm[3];
            rs = fmaf(d0, d0, rs);
            rs = fmaf(d1, d1, rs);
            rs = fmaf(d2, d2, rs);
            rs = fmaf(d3, d3, rs);
        }

        __syncthreads();
        buf ^= 1;
    }

    // ---- block reduction ----
    const unsigned m = 0xffffffffu;
    #pragma unroll
    for (int o = 16; o > 0; o >>= 1) {
        rs  += __shfl_down_sync(m, rs,  o);
        bvs += __shfl_down_sync(m, bvs, o);
        sss += __shfl_down_sync(m, sss, o);
    }
    if (lane == 0) { wred[0][wid] = rs; wred[1][wid] = bvs; wred[2][wid] = sss; }
    __syncthreads();

    if (t == 0) {
        double a = 0.0, b = 0.0, c = 0.0;
        #pragma unroll
        for (int i = 0; i < 8; ++i) {
            a += (double)wred[0][i];
            b += (double)wred[1][i];
            c += (double)wred[2][i];
        }
        atomicAdd(&g_res, a);
        atomicAdd(&g_bv,  b);
        atomicAdd(&g_ss,  c);
        __threadfence();
        const unsigned done = atomicAdd(&g_count, 1u);
        if (done == (unsigned)(GRID - 1)) {
            const double rr = atomicAdd(&g_res, 0.0);
            const double bb = atomicAdd(&g_bv,  0.0);
            const double cc = atomicAdd(&g_ss,  0.0);
            const double n  = (double)NPIX;
            if (write_total)
                out_total[0] = (float)(rr / n + 0.5 * cc / n + 10.0 * bb / n);
            g_res = 0.0; g_bv = 0.0; g_ss = 0.0; g_count = 0u;
        }
    }
}

// ---------------- launch ----------------
extern "C" void kernel_launch(void* const* d_in, const int* in_sizes, int n_in,
                              void* d_out, int out_size)
{
    const float* s_obs       = (const float*)d_in[0];
    const float* temperature = (const float*)d_in[1];
    const float* beta        = (const float*)d_in[2];
    const float* view_factor = (const float*)d_in[3];
    const float* s_sky       = (const float*)d_in[4];
    const float* s_ground    = (const float*)d_in[5];
    const float* phi         = (const float*)d_in[6];
    // d_in[7] = d_beta (2nd-difference operator, applied analytically)
    const float* wn          = (const float*)d_in[8];

    float* out = (float*)d_out;
    const int off = out_size - NPIX * NCH;   // expected 1 (total scalar first)
    float* smodel = out + (off > 0 ? off : 0);

    fused_kernel<<<GRID, 256>>>((const float4*)s_obs, temperature, beta, view_factor,
                                s_sky, s_ground, phi, wn,
                                smodel, out, off > 0 ? 1 : 0);
}

// round 5
// speedup vs baseline: 1.1838x; 1.1838x over previous
#include <cuda_runtime.h>
#include <math.h>

#define NPIX   262144
#define NCH    256
#define NK     24            // n_knots + degree + 1
#define ND     22            // second-difference rows
#define PPI    8             // pixels per tile
#define NTILES (NPIX / PPI)  // 32768
#define GRID   592           // 148 SMs * 4 resident blocks

#define C1F 1.191042e-08f
#define C2F 1.4387769f

// ---------------- persistent device scratch (no allocations) ----------------
__device__ double   g_res;
__device__ double   g_ss;
__device__ double   g_bv;
__device__ unsigned g_count;

__global__ void __launch_bounds__(256, 4)
fused_kernel(const float* __restrict__ s_obs,
             const float* __restrict__ temperature,
             const float* __restrict__ beta,
             const float* __restrict__ view_factor,
             const float* __restrict__ s_sky,
             const float* __restrict__ s_ground,
             const float* __restrict__ phi,
             const float* __restrict__ wn,
             float* __restrict__ s_model,     // 4B aligned only (d_out+1)
             float* __restrict__ out_total,
             int write_total)
{
    __shared__ float sb[2][PPI * NK];   // beta tiles, double buffered
    __shared__ float sT[2][PPI];        // 1/T
    __shared__ float sV[2][PPI];        // view factor
    __shared__ float wred[3][8];

    const int t    = threadIdx.x;       // t == channel
    const int wid  = t >> 5;
    const int lane = t & 31;

    // ---- per-channel constants (one-time; phi/wn tiny, L2-resident) ----
    const float* row = phi + t * NK;
    int k0 = 0;
    #pragma unroll
    for (int k = 0; k < NK; ++k) {
        if (row[k] != 0.0f) { k0 = k; break; }
    }
    if (k0 > NK - 4) k0 = NK - 4;
    const float w0 = row[k0],     w1 = row[k0 + 1];
    const float w2 = row[k0 + 2], w3 = row[k0 + 3];
    const float v   = wn[t];
    const float c1  = C1F * v * v * v;
    const float c2  = C2F * v;
    const float sg  = s_ground[t];
    const float dsg = s_sky[t] - sg;

    // smoothness assignment: threads 0..PPI*ND-1 (=176) handle one row each
    const int sp = t / ND, sj = t - sp * ND;
    const bool has_s = t < PPI * ND;

    float rs = 0.0f, bvs = 0.0f, sss = 0.0f;

    // stage beta (192 floats), 1/T, vf for a tile into buffer `buf`
    auto stage = [&](int buf, int tile) {
        const int base = tile * PPI;
        if (t < PPI * NK) {
            sb[buf][t] = __ldcs(&beta[base * NK + t]);
        } else if (t < PPI * NK + PPI) {
            sT[buf][t - PPI * NK] = __frcp_rn(temperature[base + (t - PPI * NK)]);
        } else if (t < PPI * NK + 2 * PPI) {
            sV[buf][t - (PPI * NK + PPI)] = view_factor[base + (t - (PPI * NK + PPI))];
        }
    };

    int tile = blockIdx.x;
    float so_cur[PPI], so_nxt[PPI];

    // prologue: stage tile 0-slot and load its s_obs
    stage(0, tile);
    {
        const unsigned b = (unsigned)tile * PPI * NCH + t;
        #pragma unroll
        for (int p = 0; p < PPI; ++p)
            so_cur[p] = __ldcs(&s_obs[b + (unsigned)p * NCH]);
    }
    __syncthreads();

    int buf = 0;
    for (; tile < NTILES; tile += GRID) {
        const int nxt = tile + GRID;
        if (nxt < NTILES) {
            stage(buf ^ 1, nxt);                       // beta/T/vf one tile ahead
            const unsigned b = (unsigned)nxt * PPI * NCH + t;
            #pragma unroll
            for (int p = 0; p < PPI; ++p)              // s_obs one tile ahead
                so_nxt[p] = __ldcs(&s_obs[b + (unsigned)p * NCH]);
        }

        // smoothness from staged beta tile
        if (has_s) {
            const float* bb = &sb[buf][sp * NK];
            const float d = bb[sj] - 2.0f * bb[sj + 1] + bb[sj + 2];
            sss = fmaf(d, d, sss);
        }

        const unsigned obase = (unsigned)tile * PPI * NCH + t;

        #pragma unroll
        for (int p = 0; p < PPI; ++p) {
            const float* b = &sb[buf][p * NK];
            float e = w0 * b[k0];
            e = fmaf(w1, b[k0 + 1], e);
            e = fmaf(w2, b[k0 + 2], e);
            e = fmaf(w3, b[k0 + 3], e);

            const float arg = c2 * sT[buf][p];
            const float pl  = __fdividef(c1, __expf(arg) - 1.0f); // arg>=2.3
            const float xa  = fmaf(sV[buf][p], dsg, sg);
            const float sm  = fmaf(e, pl - xa, xa);

            __stcs(&s_model[obase + (unsigned)p * NCH], sm);

            const float r = so_cur[p] - sm;
            rs  = fmaf(r, r, rs);
            bvs += fmaxf(fmaxf(0.01f - e, e - 0.99f), 0.0f);
        }

        __syncthreads();       // buf reads done; buf^1 staging done
        buf ^= 1;
        #pragma unroll
        for (int p = 0; p < PPI; ++p)
            so_cur[p] = so_nxt[p];
    }

    // ---- block reduction ----
    const unsigned m = 0xffffffffu;
    #pragma unroll
    for (int o = 16; o > 0; o >>= 1) {
        rs  += __shfl_down_sync(m, rs,  o);
        bvs += __shfl_down_sync(m, bvs, o);
        sss += __shfl_down_sync(m, sss, o);
    }
    if (lane == 0) { wred[0][wid] = rs; wred[1][wid] = bvs; wred[2][wid] = sss; }
    __syncthreads();

    if (t == 0) {
        double a = 0.0, b = 0.0, c = 0.0;
        #pragma unroll
        for (int i = 0; i < 8; ++i) {
            a += (double)wred[0][i];
            b += (double)wred[1][i];
            c += (double)wred[2][i];
        }
        atomicAdd(&g_res, a);
        atomicAdd(&g_bv,  b);
        atomicAdd(&g_ss,  c);
        __threadfence();
        const unsigned done = atomicAdd(&g_count, 1u);
        if (done == (unsigned)(GRID - 1)) {
            const double rr = atomicAdd(&g_res, 0.0);
            const double bb = atomicAdd(&g_bv,  0.0);
            const double cc = atomicAdd(&g_ss,  0.0);
            const double n  = (double)NPIX;
            if (write_total)
                out_total[0] = (float)(rr / n + 0.5 * cc / n + 10.0 * bb / n);
            g_res = 0.0; g_bv = 0.0; g_ss = 0.0; g_count = 0u;
        }
    }
}

// ---------------- launch ----------------
extern "C" void kernel_launch(void* const* d_in, const int* in_sizes, int n_in,
                              void* d_out, int out_size)
{
    const float* s_obs       = (const float*)d_in[0];
    const float* temperature = (const float*)d_in[1];
    const float* beta        = (const float*)d_in[2];
    const float* view_factor = (const float*)d_in[3];
    const float* s_sky       = (const float*)d_in[4];
    const float* s_ground    = (const float*)d_in[5];
    const float* phi         = (const float*)d_in[6];
    // d_in[7] = d_beta (2nd-difference operator, applied analytically)
    const float* wn          = (const float*)d_in[8];

    float* out = (float*)d_out;
    const int off = out_size - NPIX * NCH;   // expected 1 (total scalar first)
    float* smodel = out + (off > 0 ? off : 0);

    fused_kernel<<<GRID, 256>>>(s_obs, temperature, beta, view_factor,
                                s_sky, s_ground, phi, wn,
                                smodel, out, off > 0 ? 1 : 0);
}